// round 5
// baseline (speedup 1.0000x reference)
#include <cuda_runtime.h>
#include <cuda_pipeline.h>

// Geodesic loss: theta_i = acos(clip((sum(a_i*b_i)-1)*0.5, -1, 1)); out = mean(theta)
//
// R4: WARP-autonomous double-buffered cp.async pipelines.
//  - Each warp owns private chunks of 32 matrices (288 floats = 1152 B per
//    input, contiguous & coalesced), double-buffered in its own SMEM slice.
//  - Per-thread cp.async commit groups + __syncwarp only: warps never wait on
//    each other -> 48 fully independent memory streams per SM, no block-wide
//    barrier bubbles gating the load stream.
//  - Per-thread theta accumulation; one block reduction + atomicAdd at exit.

#define THREADS 256
#define NWARPS (THREADS / 32)
#define WMATS 32                    // matrices per warp-chunk
#define WFLOATS (WMATS * 9)         // 288
#define WVEC4 (WFLOATS / 4)         // 72
#define GRID_BLOCKS 888             // 6 blocks/SM x 148 SMs (SMEM-limited)

__global__ void geo_init_kernel(float* __restrict__ out) {
    out[0] = 0.0f;
}

__device__ __forceinline__ void issue_wchunk(float4* sa, float4* sb,
                                             const float4* __restrict__ a4,
                                             const float4* __restrict__ b4,
                                             long long chunk, int lane) {
    const float4* ga = a4 + chunk * WVEC4;
    const float4* gb = b4 + chunk * WVEC4;
    // 72 float4 per input, 32 lanes: lane, lane+32, and lane+64 for lane<8.
    __pipeline_memcpy_async(&sa[lane],      &ga[lane],      16);
    __pipeline_memcpy_async(&sb[lane],      &gb[lane],      16);
    __pipeline_memcpy_async(&sa[lane + 32], &ga[lane + 32], 16);
    __pipeline_memcpy_async(&sb[lane + 32], &gb[lane + 32], 16);
    if (lane < WVEC4 - 64) {
        __pipeline_memcpy_async(&sa[lane + 64], &ga[lane + 64], 16);
        __pipeline_memcpy_async(&sb[lane + 64], &gb[lane + 64], 16);
    }
}

__global__ void __launch_bounds__(THREADS)
geo_loss_kernel(const float* __restrict__ a,
                const float* __restrict__ b,
                float* __restrict__ out,
                float inv_B, long long nchunks) {
    // [warp][stage][input(a/b)][vec4]
    __shared__ float4 sbuf[NWARPS][2][2][WVEC4];
    __shared__ float wsum[NWARPS];

    const int tid = threadIdx.x;
    const int w = tid >> 5;
    const int lane = tid & 31;

    const float4* a4 = (const float4*)a;
    const float4* b4 = (const float4*)b;
    const long long total_warps = (long long)gridDim.x * NWARPS;

    float acc = 0.0f;
    long long c = (long long)blockIdx.x * NWARPS + w;

    if (c < nchunks)
        issue_wchunk((float4*)sbuf[w][0][0], (float4*)sbuf[w][0][1],
                     a4, b4, c, lane);
    __pipeline_commit();

    int st = 0;
    while (c < nchunks) {
        long long cn = c + total_warps;
        if (cn < nchunks) {
            issue_wchunk((float4*)sbuf[w][st ^ 1][0], (float4*)sbuf[w][st ^ 1][1],
                         a4, b4, cn, lane);
            __pipeline_commit();
            __pipeline_wait_prior(1);   // this thread's chunk-c group done
        } else {
            __pipeline_wait_prior(0);
        }
        __syncwarp();   // all lanes' cp.async data visible warp-wide

        // One matrix per lane: floats [lane*9, lane*9+9) of warp region.
        // Stride 9 coprime with 32 banks -> conflict-free.
        const float* pa = (const float*)sbuf[w][st][0] + lane * 9;
        const float* pb = (const float*)sbuf[w][st][1] + lane * 9;
        float dot = 0.0f;
        #pragma unroll
        for (int k = 0; k < 9; k++)
            dot = fmaf(pa[k], pb[k], dot);

        float cosv = fminf(1.0f, fmaxf(-1.0f, (dot - 1.0f) * 0.5f));
        acc += acosf(cosv);

        __syncwarp();   // all lanes done reading stage st before next overwrite
        st ^= 1;
        c = cn;
    }

    // Block reduction of per-thread accumulators.
    #pragma unroll
    for (int off = 16; off > 0; off >>= 1)
        acc += __shfl_down_sync(0xffffffffu, acc, off);
    if (lane == 0)
        wsum[w] = acc;
    __syncthreads();

    if (tid < NWARPS) {
        float v = wsum[tid];
        #pragma unroll
        for (int off = NWARPS / 2; off > 0; off >>= 1)
            v += __shfl_down_sync((1u << NWARPS) - 1u, v, off);
        if (tid == 0)
            atomicAdd(out, v * inv_B);
    }
}

extern "C" void kernel_launch(void* const* d_in, const int* in_sizes, int n_in,
                              void* d_out, int out_size) {
    const float* a = (const float*)d_in[0];  // pred_rot, B*9 floats
    const float* b = (const float*)d_in[1];  // gt_rot,   B*9 floats
    float* out = (float*)d_out;

    const long long n_elems = in_sizes[0];
    const long long B = n_elems / 9;
    const long long nchunks = B / WMATS;     // 65536 (B = 2^21 divides evenly)

    geo_init_kernel<<<1, 1>>>(out);
    geo_loss_kernel<<<GRID_BLOCKS, THREADS>>>(a, b, out, 1.0f / (float)B, nchunks);
}

// round 6
// speedup vs baseline: 1.0291x; 1.0291x over previous
#include <cuda_runtime.h>
#include <cuda_pipeline.h>

// Geodesic loss: theta_i = acos(clip((sum(a_i*b_i)-1)*0.5, -1, 1)); out = mean(theta)
//
// R5: single-kernel (init launch removed via last-block-done reduction).
//  - Core unchanged from R4: warp-autonomous double-buffered cp.async
//    pipelines, pinned at the LTS (~6300 B/cyc) chip throughput floor.
//  - Block partials -> __device__ accumulator; fenced counter elects the last
//    block, which writes d_out and resets the globals (replay-deterministic).

#define THREADS 256
#define NWARPS (THREADS / 32)
#define WMATS 32                    // matrices per warp-chunk
#define WFLOATS (WMATS * 9)         // 288
#define WVEC4 (WFLOATS / 4)         // 72
#define GRID_BLOCKS 888             // 6 blocks/SM x 148 SMs (SMEM-limited)

__device__ float g_acc = 0.0f;
__device__ unsigned int g_ctr = 0;

__device__ __forceinline__ void issue_wchunk(float4* sa, float4* sb,
                                             const float4* __restrict__ a4,
                                             const float4* __restrict__ b4,
                                             long long chunk, int lane) {
    const float4* ga = a4 + chunk * WVEC4;
    const float4* gb = b4 + chunk * WVEC4;
    // 72 float4 per input, 32 lanes: lane, lane+32, and lane+64 for lane<8.
    __pipeline_memcpy_async(&sa[lane],      &ga[lane],      16);
    __pipeline_memcpy_async(&sb[lane],      &gb[lane],      16);
    __pipeline_memcpy_async(&sa[lane + 32], &ga[lane + 32], 16);
    __pipeline_memcpy_async(&sb[lane + 32], &gb[lane + 32], 16);
    if (lane < WVEC4 - 64) {
        __pipeline_memcpy_async(&sa[lane + 64], &ga[lane + 64], 16);
        __pipeline_memcpy_async(&sb[lane + 64], &gb[lane + 64], 16);
    }
}

__global__ void __launch_bounds__(THREADS)
geo_loss_kernel(const float* __restrict__ a,
                const float* __restrict__ b,
                float* __restrict__ out,
                float inv_B, long long nchunks) {
    // [warp][stage][input(a/b)][vec4]
    __shared__ float4 sbuf[NWARPS][2][2][WVEC4];
    __shared__ float wsum[NWARPS];

    const int tid = threadIdx.x;
    const int w = tid >> 5;
    const int lane = tid & 31;

    const float4* a4 = (const float4*)a;
    const float4* b4 = (const float4*)b;
    const long long total_warps = (long long)gridDim.x * NWARPS;

    float acc = 0.0f;
    long long c = (long long)blockIdx.x * NWARPS + w;

    if (c < nchunks)
        issue_wchunk((float4*)sbuf[w][0][0], (float4*)sbuf[w][0][1],
                     a4, b4, c, lane);
    __pipeline_commit();

    int st = 0;
    while (c < nchunks) {
        long long cn = c + total_warps;
        if (cn < nchunks) {
            issue_wchunk((float4*)sbuf[w][st ^ 1][0], (float4*)sbuf[w][st ^ 1][1],
                         a4, b4, cn, lane);
            __pipeline_commit();
            __pipeline_wait_prior(1);   // this thread's chunk-c group done
        } else {
            __pipeline_wait_prior(0);
        }
        __syncwarp();   // all lanes' cp.async data visible warp-wide

        // One matrix per lane: floats [lane*9, lane*9+9) of warp region.
        // Stride 9 coprime with 32 banks -> conflict-free.
        const float* pa = (const float*)sbuf[w][st][0] + lane * 9;
        const float* pb = (const float*)sbuf[w][st][1] + lane * 9;
        float dot = 0.0f;
        #pragma unroll
        for (int k = 0; k < 9; k++)
            dot = fmaf(pa[k], pb[k], dot);

        float cosv = fminf(1.0f, fmaxf(-1.0f, (dot - 1.0f) * 0.5f));
        acc += acosf(cosv);

        __syncwarp();   // all lanes done reading stage st before next overwrite
        st ^= 1;
        c = cn;
    }

    // Block reduction of per-thread accumulators.
    #pragma unroll
    for (int off = 16; off > 0; off >>= 1)
        acc += __shfl_down_sync(0xffffffffu, acc, off);
    if (lane == 0)
        wsum[w] = acc;
    __syncthreads();

    if (tid == 0) {
        float v = 0.0f;
        #pragma unroll
        for (int i = 0; i < NWARPS; i++)
            v += wsum[i];

        // Accumulate into device-global, elect last block via fenced counter.
        atomicAdd(&g_acc, v);
        __threadfence();
        unsigned int old = atomicAdd(&g_ctr, 1u);
        if (old == (unsigned int)gridDim.x - 1u) {
            // All blocks' adds are visible (their fences precede their incs).
            out[0] = g_acc * inv_B;
            // Reset for the next graph replay (deterministic across launches).
            g_acc = 0.0f;
            __threadfence();
            g_ctr = 0u;
        }
    }
}

extern "C" void kernel_launch(void* const* d_in, const int* in_sizes, int n_in,
                              void* d_out, int out_size) {
    const float* a = (const float*)d_in[0];  // pred_rot, B*9 floats
    const float* b = (const float*)d_in[1];  // gt_rot,   B*9 floats
    float* out = (float*)d_out;

    const long long n_elems = in_sizes[0];
    const long long B = n_elems / 9;
    const long long nchunks = B / WMATS;     // 65536 (B = 2^21 divides evenly)

    geo_loss_kernel<<<GRID_BLOCKS, THREADS>>>(a, b, out, 1.0f / (float)B, nchunks);
}